// round 10
// baseline (speedup 1.0000x reference)
#include <cuda_runtime.h>

// ReactDiffDynamics: per batch b (64), channels U,V of 512x512 fp32 (periodic):
//   dUdt = a*lap(U) + U - U^3 - k - V
//   dVdt = b*lap(V) + U - V
// lap = 5-point periodic stencil / dx^2, dx = 0.06451612903.
//
// R10: R9 (RPT=4 row-marching, no prefetch, shuffle halo, streaming stores)
// with one more occupancy notch: __launch_bounds__(256, 6) -> ptxas targets
// ~42 regs -> 6 blocks/SM. Occupancy->DRAM%% curve measured so far:
// 26%->64.8, 40%->70.5, 52%->71.9; bytes are floored at ~214 MB/replay, so
// DRAM efficiency is the only lever left.

#define RD_W  512
#define RD_HW (512 * 512)
#define RPT   4

__global__ __launch_bounds__(256, 6) void react_diff_kernel(
    const float* __restrict__ x,
    const float* __restrict__ params,
    float* __restrict__ out)
{
    const float inv_dx2 = 1.0f / (0.06451612903f * 0.06451612903f); // 240.25

    int t    = blockIdx.x * blockDim.x + threadIdx.x; // 0 .. 2^20-1
    int xq   = t & 127;           // float4 group within row
    int tile = (t >> 7) & 127;    // 4-row tile index (512/4 = 128)
    int b    = t >> 14;           // batch
    int lane = threadIdx.x & 31;

    const float* Ubase = x + (size_t)b * 2 * RD_HW;
    const float* Vbase = Ubase + RD_HW;
    float* OU = out + (size_t)b * 2 * RD_HW;
    float* OV = OU + RD_HW;

    float pa = __ldg(&params[b * 3 + 0]);
    float pb = __ldg(&params[b * 3 + 1]);
    float pk = __ldg(&params[b * 3 + 2]);

    int y0 = tile * RPT;
    int x0 = xq << 2;
    int xl = (x0 - 1) & 511;
    int xr = (x0 + 4) & 511;

    #define LDU(y) (((const float4*)(Ubase + (size_t)(y) * RD_W))[xq])
    #define LDV(y) (((const float4*)(Vbase + (size_t)(y) * RD_W))[xq])

    float4 Uu = LDU((y0 - 1) & 511);
    float4 Uc = LDU(y0);
    float4 Vu = LDV((y0 - 1) & 511);
    float4 Vc = LDV(y0);

    #pragma unroll
    for (int r = 0; r < RPT; r++) {
        int y = y0 + r;
        int yd = (y + 1) & 511;
        float4 Ud = LDU(yd);
        float4 Vd = LDV(yd);

        // horizontal neighbors via shuffle; warp-edge lanes load scalar
        float Ul = __shfl_up_sync(0xFFFFFFFFu, Uc.w, 1);
        float Vl = __shfl_up_sync(0xFFFFFFFFu, Vc.w, 1);
        float Ur = __shfl_down_sync(0xFFFFFFFFu, Uc.x, 1);
        float Vr = __shfl_down_sync(0xFFFFFFFFu, Vc.x, 1);
        if (lane == 0) {
            Ul = Ubase[(size_t)y * RD_W + xl];
            Vl = Vbase[(size_t)y * RD_W + xl];
        }
        if (lane == 31) {
            Ur = Ubase[(size_t)y * RD_W + xr];
            Vr = Vbase[(size_t)y * RD_W + xr];
        }

        float4 lapU, lapV;
        lapU.x = (Ul   + Uc.y + Uu.x + Ud.x - 4.0f * Uc.x) * inv_dx2;
        lapU.y = (Uc.x + Uc.z + Uu.y + Ud.y - 4.0f * Uc.y) * inv_dx2;
        lapU.z = (Uc.y + Uc.w + Uu.z + Ud.z - 4.0f * Uc.z) * inv_dx2;
        lapU.w = (Uc.z + Ur   + Uu.w + Ud.w - 4.0f * Uc.w) * inv_dx2;

        lapV.x = (Vl   + Vc.y + Vu.x + Vd.x - 4.0f * Vc.x) * inv_dx2;
        lapV.y = (Vc.x + Vc.z + Vu.y + Vd.y - 4.0f * Vc.y) * inv_dx2;
        lapV.z = (Vc.y + Vc.w + Vu.z + Vd.z - 4.0f * Vc.z) * inv_dx2;
        lapV.w = (Vc.z + Vr   + Vu.w + Vd.w - 4.0f * Vc.w) * inv_dx2;

        float4 dU, dV;
        dU.x = pa * lapU.x + Uc.x - Uc.x * Uc.x * Uc.x - pk - Vc.x;
        dU.y = pa * lapU.y + Uc.y - Uc.y * Uc.y * Uc.y - pk - Vc.y;
        dU.z = pa * lapU.z + Uc.z - Uc.z * Uc.z * Uc.z - pk - Vc.z;
        dU.w = pa * lapU.w + Uc.w - Uc.w * Uc.w * Uc.w - pk - Vc.w;

        dV.x = pb * lapV.x + Uc.x - Vc.x;
        dV.y = pb * lapV.y + Uc.y - Vc.y;
        dV.z = pb * lapV.z + Uc.z - Vc.z;
        dV.w = pb * lapV.w + Uc.w - Vc.w;

        __stcs((float4*)(OU + (size_t)y * RD_W) + xq, dU);
        __stcs((float4*)(OV + (size_t)y * RD_W) + xq, dV);

        // rotate rows
        Uu = Uc; Uc = Ud;
        Vu = Vc; Vc = Vd;
    }
    #undef LDU
    #undef LDV
}

extern "C" void kernel_launch(void* const* d_in, const int* in_sizes, int n_in,
                              void* d_out, int out_size)
{
    const float* x      = (const float*)d_in[1];
    const float* params = (const float*)d_in[2];
    float* out          = (float*)d_out;

    // 64 batches * 128 row-tiles * 128 groups = 2^20 threads
    const int threads = 256;
    const int blocks  = (64 * 128 * 128) / threads; // 4096
    react_diff_kernel<<<blocks, threads>>>(x, params, out);
}